// round 3
// baseline (speedup 1.0000x reference)
#include <cuda_runtime.h>

// Problem constants
#define H_ 128
#define W_ 128
#define C_ 32
#define BS_ 8
#define NKP_ 11                      // num_kp + 1
#define NPIX_ (BS_ * NKP_ * H_ * W_) // 1,441,792 pixels
#define PIX_PER_BLOCK_ 256
#define NBLOCKS_ (NPIX_ / PIX_PER_BLOCK_)   // 5632

__global__ void __launch_bounds__(256) deform_kernel(
    const float* __restrict__ src,   // (H, W, C) = (128,128,32)
    const float* __restrict__ mot,   // (NPIX, 2)
    float* __restrict__ out)         // (NPIX, C)
{
    __shared__ float4 s_w[PIX_PER_BLOCK_];   // corner weights (nw, ne, sw, se)
    __shared__ int4   s_o[PIX_PER_BLOCK_];   // clamped float-base offsets per corner

    const int t = threadIdx.x;
    const int blockPix = blockIdx.x * PIX_PER_BLOCK_;

    // ---- Phase 1: all 256 threads compute weights + offsets, 1 pixel each ----
    {
        const int pix = blockPix + t;
        float2 g = __ldg(((const float2*)mot) + pix);
        float gx = fmaf(g.x, (float)(W_ / 2), (float)(W_ / 2) - 0.5f);
        float gy = fmaf(g.y, (float)(H_ / 2), (float)(H_ / 2) - 0.5f);

        float xwf = floorf(gx);
        float ynf = floorf(gy);
        float fx = gx - xwf;     // 'w'
        float fy = gy - ynf;     // 'n'
        float ex = 1.0f - fx;    // 'e'
        float sy = 1.0f - fy;    // 's'

        int x0 = (int)xwf;
        int y0 = (int)ynf;
        int x1 = x0 + 1;
        int y1 = y0 + 1;

        bool mx0 = (x0 >= 0) & (x0 < W_);
        bool mx1 = (x1 >= 0) & (x1 < W_);
        bool my0 = (y0 >= 0) & (y0 < H_);
        bool my1 = (y1 >= 0) & (y1 < H_);

        float4 w;
        w.x = sy * ex * (float)(my0 & mx0);  // nw
        w.y = sy * fx * (float)(my0 & mx1);  // ne
        w.z = fy * ex * (float)(my1 & mx0);  // sw
        w.w = fy * fx * (float)(my1 & mx1);  // se

        int xc0 = mx0 ? x0 : 0;
        int xc1 = mx1 ? x1 : 0;
        int yc0 = my0 ? y0 : 0;
        int yc1 = my1 ? y1 : 0;

        int4 o;
        o.x = (yc0 * W_ + xc0) << 5;   // float index of (y0,x0,c=0)
        o.y = (yc0 * W_ + xc1) << 5;
        o.z = (yc1 * W_ + xc0) << 5;
        o.w = (yc1 * W_ + xc1) << 5;

        s_w[t] = w;
        s_o[t] = o;
    }
    __syncthreads();

    // ---- Phase 2: warp = 1 pixel at a time, 32 lanes = 32 channels.
    //      All global loads are warp-uniform 128B lines: 1 wavefront, no replay.
    const int warp = t >> 5;
    const int lane = t & 31;
    const int pbase = warp << 5;               // this warp's 32 pixels

    float* outBase = out + ((blockPix + pbase) << 5) + lane;

    #pragma unroll 4
    for (int p = 0; p < 32; ++p) {
        float4 w = s_w[pbase + p];
        int4   o = s_o[pbase + p];

        float v00 = __ldg(src + o.x + lane);
        float v01 = __ldg(src + o.y + lane);
        float v10 = __ldg(src + o.z + lane);
        float v11 = __ldg(src + o.w + lane);

        float acc = fmaf(w.x, v00, fmaf(w.y, v01, fmaf(w.z, v10, w.w * v11)));
        outBase[p << 5] = acc;
    }
}

extern "C" void kernel_launch(void* const* d_in, const int* in_sizes, int n_in,
                              void* d_out, int out_size)
{
    const float* src = (const float*)d_in[0];   // source (1,H,W,C)
    const float* mot = (const float*)d_in[1];   // motions (BS,NKP,H,W,2)
    float* out = (float*)d_out;

    deform_kernel<<<NBLOCKS_, 256>>>(src, mot, out);
}

// round 4
// speedup vs baseline: 1.0104x; 1.0104x over previous
#include <cuda_runtime.h>

// Problem constants
#define H_ 128
#define W_ 128
#define C_ 32
#define BS_ 8
#define NKP_ 11                      // num_kp + 1
#define NPIX_ (BS_ * NKP_ * H_ * W_) // 1,441,792 pixels
#define PIX_PER_BLOCK_ 256
#define NBLOCKS_ (NPIX_ / PIX_PER_BLOCK_)   // 5632

__global__ void __launch_bounds__(256) deform_kernel(
    const float* __restrict__ src,   // (H, W, C) = (128,128,32)
    const float* __restrict__ mot,   // (NPIX, 2)
    float* __restrict__ out)         // (NPIX, C)
{
    __shared__ float4 s_w[PIX_PER_BLOCK_];   // corner weights (nw, ne, sw, se)
    __shared__ int4   s_o[PIX_PER_BLOCK_];   // clamped float-base offsets per corner

    const int t = threadIdx.x;
    const int blockPix = blockIdx.x * PIX_PER_BLOCK_;

    // ---- Phase 1: all 256 threads compute weights + offsets, 1 pixel each ----
    {
        const int pix = blockPix + t;
        float2 g = __ldg(((const float2*)mot) + pix);
        float gx = fmaf(g.x, (float)(W_ / 2), (float)(W_ / 2) - 0.5f);
        float gy = fmaf(g.y, (float)(H_ / 2), (float)(H_ / 2) - 0.5f);

        float xwf = floorf(gx);
        float ynf = floorf(gy);
        float fx = gx - xwf;     // 'w'
        float fy = gy - ynf;     // 'n'
        float ex = 1.0f - fx;    // 'e'
        float sy = 1.0f - fy;    // 's'

        int x0 = (int)xwf;
        int y0 = (int)ynf;
        int x1 = x0 + 1;
        int y1 = y0 + 1;

        bool mx0 = (x0 >= 0) & (x0 < W_);
        bool mx1 = (x1 >= 0) & (x1 < W_);
        bool my0 = (y0 >= 0) & (y0 < H_);
        bool my1 = (y1 >= 0) & (y1 < H_);

        float4 w;
        w.x = sy * ex * (float)(my0 & mx0);  // nw
        w.y = sy * fx * (float)(my0 & mx1);  // ne
        w.z = fy * ex * (float)(my1 & mx0);  // sw
        w.w = fy * fx * (float)(my1 & mx1);  // se

        int xc0 = mx0 ? x0 : 0;
        int xc1 = mx1 ? x1 : 0;
        int yc0 = my0 ? y0 : 0;
        int yc1 = my1 ? y1 : 0;

        int4 o;
        o.x = (yc0 * W_ + xc0) << 5;   // float index of (y0,x0,c=0)
        o.y = (yc0 * W_ + xc1) << 5;
        o.z = (yc1 * W_ + xc0) << 5;
        o.w = (yc1 * W_ + xc1) << 5;

        s_w[t] = w;
        s_o[t] = o;
    }
    __syncthreads();

    // ---- Phase 2: warp = 1 pixel at a time, 32 lanes = 32 channels.
    //      All global loads are warp-uniform 128B lines: 1 wavefront, no replay.
    const int warp = t >> 5;
    const int lane = t & 31;
    const int pbase = warp << 5;               // this warp's 32 pixels

    float* outBase = out + ((blockPix + pbase) << 5) + lane;

    #pragma unroll 4
    for (int p = 0; p < 32; ++p) {
        float4 w = s_w[pbase + p];
        int4   o = s_o[pbase + p];

        float v00 = __ldg(src + o.x + lane);
        float v01 = __ldg(src + o.y + lane);
        float v10 = __ldg(src + o.z + lane);
        float v11 = __ldg(src + o.w + lane);

        float acc = fmaf(w.x, v00, fmaf(w.y, v01, fmaf(w.z, v10, w.w * v11)));
        outBase[p << 5] = acc;
    }
}

extern "C" void kernel_launch(void* const* d_in, const int* in_sizes, int n_in,
                              void* d_out, int out_size)
{
    const float* src = (const float*)d_in[0];   // source (1,H,W,C)
    const float* mot = (const float*)d_in[1];   // motions (BS,NKP,H,W,2)
    float* out = (float*)d_out;

    deform_kernel<<<NBLOCKS_, 256>>>(src, mot, out);
}

// round 6
// speedup vs baseline: 1.0118x; 1.0014x over previous
#include <cuda_runtime.h>

// Problem constants
#define H_ 128
#define W_ 128
#define C_ 32
#define NPIX_ (8 * 11 * 128 * 128)   // 1,441,792 pixels
#define PPB_ 256                     // pixels per block
#define NBLOCKS_ (NPIX_ / PPB_)      // 5632

__global__ void __launch_bounds__(256, 1) deform_kernel(
    const float* __restrict__ src,   // (H, W, C) = (128,128,32)
    const float* __restrict__ mot,   // (NPIX, 2)
    float* __restrict__ out)         // (NPIX, C)
{
    __shared__ float4 s_w[PPB_];     // corner weights (nw, ne, sw, se)
    __shared__ int4   s_o[PPB_];     // clamped element offsets (c=0) per corner

    const int t = threadIdx.x;
    const int blockPix = blockIdx.x * PPB_;

    // ---- Phase 1: all 256 threads compute weights + offsets, 1 pixel each ----
    {
        const int pix = blockPix + t;
        float2 g = __ldg(((const float2*)mot) + pix);
        float gx = fmaf(g.x, 64.0f, 63.5f);   // (g+1)*64 - 0.5
        float gy = fmaf(g.y, 64.0f, 63.5f);

        float xwf = floorf(gx);
        float ynf = floorf(gy);
        float fx = gx - xwf;     // 'w'
        float fy = gy - ynf;     // 'n'
        float ex = 1.0f - fx;    // 'e'
        float sy = 1.0f - fy;    // 's'

        int x0 = (int)xwf;
        int y0 = (int)ynf;
        int x1 = x0 + 1;
        int y1 = y0 + 1;

        // unsigned compare: (x >= 0 && x < N) == ((unsigned)x < N)
        bool mx0 = (unsigned)x0 < (unsigned)W_;
        bool mx1 = (unsigned)x1 < (unsigned)W_;
        bool my0 = (unsigned)y0 < (unsigned)H_;
        bool my1 = (unsigned)y1 < (unsigned)H_;

        float4 w;
        w.x = sy * ex * (float)(my0 & mx0);  // nw
        w.y = sy * fx * (float)(my0 & mx1);  // ne
        w.z = fy * ex * (float)(my1 & mx0);  // sw
        w.w = fy * fx * (float)(my1 & mx1);  // se

        int xc0 = mx0 ? x0 : 0;
        int xc1 = mx1 ? x1 : 0;
        int yc0 = my0 ? y0 : 0;
        int yc1 = my1 ? y1 : 0;

        int4 o;
        o.x = (yc0 * W_ + xc0) << 5;   // element offset of (y0,x0,c=0)
        o.y = (yc0 * W_ + xc1) << 5;
        o.z = (yc1 * W_ + xc0) << 5;
        o.w = (yc1 * W_ + xc1) << 5;

        s_w[t] = w;
        s_o[t] = o;
    }
    __syncthreads();

    // ---- Phase 2: warp = 1 pixel/iter, 32 lanes = 32 channels.
    //      srcL hoists the lane offset so each corner load is one
    //      IMAD.WIDE (fma pipe) + LDG (uniform line, 1 wavefront).
    const int warp = t >> 5;
    const int lane = t & 31;
    const int pbase = warp << 5;

    const float*  __restrict__ srcL = src + lane;
    float*        __restrict__ outp = out + ((blockPix + pbase) << 5) + lane;
    const float4* __restrict__ wp = s_w + pbase;
    const int4*   __restrict__ op = s_o + pbase;

    #pragma unroll 4
    for (int p = 0; p < 32; ++p) {
        float4 w = wp[p];
        int4   o = op[p];

        float v00 = __ldg(srcL + o.x);
        float v01 = __ldg(srcL + o.y);
        float v10 = __ldg(srcL + o.z);
        float v11 = __ldg(srcL + o.w);

        outp[p << 5] =
            fmaf(w.x, v00, fmaf(w.y, v01, fmaf(w.z, v10, w.w * v11)));
    }
}

extern "C" void kernel_launch(void* const* d_in, const int* in_sizes, int n_in,
                              void* d_out, int out_size)
{
    const float* src = (const float*)d_in[0];   // source (1,H,W,C)
    const float* mot = (const float*)d_in[1];   // motions (BS,NKP,H,W,2)
    float* out = (float*)d_out;

    deform_kernel<<<NBLOCKS_, 256>>>(src, mot, out);
}